// round 14
// baseline (speedup 1.0000x reference)
#include <cuda_runtime.h>
#include <cstdint>

#define D 96
#define MAX_N 50000
#define MAXDEG 64
#define MAX_OVF 4096

// ---- scratch (static device globals; no allocation) -----------------------
__device__ uint32_t g_xt[MAX_N * D];            // tf32-rounded x bits
__device__ float    g_y[MAX_N * D];             // y = x @ W^T (fp32)
__device__ uint32_t g_wt[D * D];                // tf32-rounded W bits
__device__ int      g_cnt[MAX_N];               // per-node cursor / degree
__device__ int2     g_pack[MAX_N * MAXDEG];     // (src, bitcast(w)) buckets
__device__ int      g_ovfcnt;
__device__ int4     g_ovf[MAX_OVF];             // (src, dst, bitcast(w), pad)

__device__ __forceinline__ uint32_t tf32_bits(float x) {
    uint32_t u;
    asm("cvt.rna.tf32.f32 %0, %1;" : "=r"(u) : "f"(x));
    return u;
}
__device__ __forceinline__ uint32_t smem_u32(const void* p) {
    uint32_t a;
    asm("{ .reg .u64 t; cvta.to.shared.u64 t, %1; cvt.u32.u64 %0, t; }"
        : "=r"(a) : "l"(p));
    return a;
}

// ---------------------------------------------------------------------------
// K0 (stream 0): convert x (and W, in the first blocks) to tf32 bit patterns.
// ---------------------------------------------------------------------------
__global__ void xconv_kernel(const float* __restrict__ x,
                             const float* __restrict__ Wm, int n4) {
    int i = blockIdx.x * blockDim.x + threadIdx.x;
    if (i < D * D / 4) {
        float4 v = __ldg(reinterpret_cast<const float4*>(Wm) + i);
        uint4 u = make_uint4(tf32_bits(v.x), tf32_bits(v.y),
                             tf32_bits(v.z), tf32_bits(v.w));
        reinterpret_cast<uint4*>(g_wt)[i] = u;
    }
    if (i < n4) {
        float4 v = __ldg(reinterpret_cast<const float4*>(x) + i);
        uint4 u = make_uint4(tf32_bits(v.x), tf32_bits(v.y),
                             tf32_bits(v.z), tf32_bits(v.w));
        reinterpret_cast<uint4*>(g_xt)[i] = u;
    }
}

// ---------------------------------------------------------------------------
// K1 (stream 2): zero cursors + overflow counter.
// ---------------------------------------------------------------------------
__global__ void zero_kernel(int N) {
    int i = blockIdx.x * blockDim.x + threadIdx.x;
    if (i < N) g_cnt[i] = 0;
    if (i == 0) g_ovfcnt = 0;
}

// ---------------------------------------------------------------------------
// K2 (stream 2): bucket edges. EPT=4 (measured best).
// ---------------------------------------------------------------------------
#define EPT 4
__global__ void bucket_kernel(const int* __restrict__ ei,
                              const float* __restrict__ ew,
                              const float* __restrict__ pr,
                              int E) {
    int base = (blockIdx.x * blockDim.x + threadIdx.x) * EPT;
    int src[EPT], dst[EPT];
    float w[EPT];
#pragma unroll
    for (int u = 0; u < EPT; u++) {
        int e = base + u;
        if (e < E) { src[u] = __ldg(ei + e); dst[u] = __ldg(ei + E + e); w[u] = __ldg(ew + e); }
    }
#pragma unroll
    for (int u = 0; u < EPT; u++) {
        int e = base + u;
        if (e < E) w[u] *= __ldg(pr + src[u]);
    }
#pragma unroll
    for (int u = 0; u < EPT; u++) {
        int e = base + u;
        if (e < E) {
            int pos = atomicAdd(&g_cnt[dst[u]], 1);
            if (pos < MAXDEG) {
                g_pack[dst[u] * MAXDEG + pos] = make_int2(src[u], __float_as_int(w[u]));
            } else {
                int o = atomicAdd(&g_ovfcnt, 1);
                if (o < MAX_OVF)
                    g_ovf[o] = make_int4(src[u], dst[u], __float_as_int(w[u]), 0);
            }
        }
    }
}

// ---------------------------------------------------------------------------
// K3 (stream 0): y = x @ W^T — grid-strided, double-buffered tf32 mma GEMM.
// Identical structure to the proven R13 kernel; source g_xt, sink g_y, no bias.
// ---------------------------------------------------------------------------
#define LDP 100
#define NTILE 64
__global__ __launch_bounds__(256, 2)
void gemm_y_kernel(int N, int ntiles) {
    extern __shared__ uint32_t smem[];
    uint32_t* sW = smem;                     // [96][LDP]
    uint32_t* sA0 = smem + D * LDP;          // [64][LDP] buffer 0
    uint32_t* sA1 = sA0 + NTILE * LDP;       // [64][LDP] buffer 1
    uint32_t sW_b  = smem_u32(sW);
    uint32_t sA0_b = smem_u32(sA0);
    uint32_t sA1_b = smem_u32(sA1);

    int t   = threadIdx.x;
    int lid = t & 31;
    int wid = t >> 5;
    int m0  = (wid & 1) * 32;
    int n0  = (wid >> 1) * 24;
    int arow = lid >> 2;
    int acol = lid & 3;

    int stride = gridDim.x;

    auto fill_A = [&](int tile, uint32_t buf_b) {
        int row0 = tile * NTILE;
        for (int i = t; i < NTILE * (D / 4); i += 256) {
            int r = i / (D / 4), c4 = i % (D / 4);
            int gr = row0 + r;
            const uint32_t* src = g_xt + (size_t)gr * D + c4 * 4;
            uint32_t dst = buf_b + (uint32_t)(r * LDP + c4 * 4) * 4u;
            int sz = (gr < N) ? 16 : 0;
            asm volatile("cp.async.cg.shared.global [%0], [%1], 16, %2;"
                         :: "r"(dst), "l"(src), "r"(sz));
        }
    };

    for (int i = t; i < D * (D / 4); i += 256) {
        int r = i / (D / 4), c4 = i % (D / 4);
        const uint32_t* src = g_wt + (size_t)r * D + c4 * 4;
        uint32_t dst = sW_b + (uint32_t)(r * LDP + c4 * 4) * 4u;
        asm volatile("cp.async.cg.shared.global [%0], [%1], 16;"
                     :: "r"(dst), "l"(src));
    }
    int tile0 = blockIdx.x;
    if (tile0 < ntiles) fill_A(tile0, sA0_b);
    asm volatile("cp.async.commit_group;");

    int pipe = 0;
    for (int tile = tile0; tile < ntiles; tile += stride) {
        uint32_t* sA = pipe ? sA1 : sA0;

        asm volatile("cp.async.wait_group 0;");
        __syncthreads();

        int next = tile + stride;
        if (next < ntiles) fill_A(next, pipe ? sA0_b : sA1_b);
        asm volatile("cp.async.commit_group;");

        int row0 = tile * NTILE;

        float c[2][3][4];
#pragma unroll
        for (int mt = 0; mt < 2; mt++)
#pragma unroll
            for (int nt = 0; nt < 3; nt++)
#pragma unroll
                for (int q = 0; q < 4; q++) c[mt][nt][q] = 0.f;

#pragma unroll
        for (int ks = 0; ks < 12; ks++) {
            int k0 = ks * 8;
            uint32_t a[2][4];
#pragma unroll
            for (int mt = 0; mt < 2; mt++) {
                const uint32_t* base = sA + (m0 + mt * 16 + arow) * LDP + k0 + acol;
                a[mt][0] = base[0];
                a[mt][1] = base[8 * LDP];
                a[mt][2] = base[4];
                a[mt][3] = base[8 * LDP + 4];
            }
            uint32_t bfr[3][2];
#pragma unroll
            for (int nt = 0; nt < 3; nt++) {
                const uint32_t* base = sW + (n0 + nt * 8 + arow) * LDP + k0 + acol;
                bfr[nt][0] = base[0];
                bfr[nt][1] = base[4];
            }
#pragma unroll
            for (int mt = 0; mt < 2; mt++)
#pragma unroll
                for (int nt = 0; nt < 3; nt++) {
                    asm volatile(
                        "mma.sync.aligned.m16n8k8.row.col.f32.tf32.tf32.f32 "
                        "{%0,%1,%2,%3}, {%4,%5,%6,%7}, {%8,%9}, {%0,%1,%2,%3};"
                        : "+f"(c[mt][nt][0]), "+f"(c[mt][nt][1]),
                          "+f"(c[mt][nt][2]), "+f"(c[mt][nt][3])
                        : "r"(a[mt][0]), "r"(a[mt][1]), "r"(a[mt][2]), "r"(a[mt][3]),
                          "r"(bfr[nt][0]), "r"(bfr[nt][1]));
                }
        }

#pragma unroll
        for (int nt = 0; nt < 3; nt++) {
            int col = n0 + nt * 8 + 2 * acol;
#pragma unroll
            for (int mt = 0; mt < 2; mt++) {
                int r_lo = row0 + m0 + mt * 16 + arow;
                if (r_lo < N) {
                    float2 v = make_float2(c[mt][nt][0], c[mt][nt][1]);
                    *reinterpret_cast<float2*>(g_y + (size_t)r_lo * D + col) = v;
                }
                int r_hi = r_lo + 8;
                if (r_hi < N) {
                    float2 v = make_float2(c[mt][nt][2], c[mt][nt][3]);
                    *reinterpret_cast<float2*>(g_y + (size_t)r_hi * D + col) = v;
                }
            }
        }

        __syncthreads();
        pipe ^= 1;
    }
}

// ---------------------------------------------------------------------------
// K4 (after join): out[node] = sum_e w_e * y[src_e] + y[node] + b.
// R8 aggregation structure (smem staging, unroll-4, high occupancy), but
// gathers y and writes the FINAL output directly.
// ---------------------------------------------------------------------------
__global__ void aggregate_kernel(const float* __restrict__ bias,
                                 float* __restrict__ out, int N) {
    __shared__ int2 s_pack[8][MAXDEG];

    int wid  = threadIdx.x >> 5;
    int l    = threadIdx.x & 31;
    int node = blockIdx.x * 8 + wid;
    if (node >= N) return;

    int cnt = g_cnt[node];
    if (cnt > MAXDEG) cnt = MAXDEG;

    const int2* bucket = g_pack + (size_t)node * MAXDEG;
    for (int k = l; k < cnt; k += 32)
        s_pack[wid][k] = __ldg(bucket + k);
    __syncwarp();

    const float* yr0 = g_y + (size_t)node * D;
    float a0 = yr0[l]      + __ldg(bias + l);
    float a1 = yr0[32 + l] + __ldg(bias + 32 + l);
    float a2 = yr0[64 + l] + __ldg(bias + 64 + l);

    int j = 0;
    for (; j + 4 <= cnt; j += 4) {
        int   s[4]; float w[4];
#pragma unroll
        for (int u = 0; u < 4; u++) {
            int2 p = s_pack[wid][j + u];
            s[u] = p.x; w[u] = __int_as_float(p.y);
        }
        float b0[4], b1[4], b2[4];
#pragma unroll
        for (int u = 0; u < 4; u++) {
            const float* yr = g_y + (size_t)s[u] * D;
            b0[u] = yr[l];
            b1[u] = yr[32 + l];
            b2[u] = yr[64 + l];
        }
#pragma unroll
        for (int u = 0; u < 4; u++) {
            a0 += w[u] * b0[u];
            a1 += w[u] * b1[u];
            a2 += w[u] * b2[u];
        }
    }
    for (; j < cnt; j++) {
        int2 p = s_pack[wid][j];
        float w = __int_as_float(p.y);
        const float* yr = g_y + (size_t)p.x * D;
        a0 += w * yr[l];
        a1 += w * yr[32 + l];
        a2 += w * yr[64 + l];
    }

    int ovf = g_ovfcnt;
    if (ovf > 0) {
        if (ovf > MAX_OVF) ovf = MAX_OVF;
        for (int i = 0; i < ovf; i++) {
            int4 p = g_ovf[i];
            if (p.y == node) {
                float w = __int_as_float(p.z);
                const float* yr = g_y + (size_t)p.x * D;
                a0 += w * yr[l];
                a1 += w * yr[32 + l];
                a2 += w * yr[64 + l];
            }
        }
    }

    float* o = out + (size_t)node * D;
    o[l]      = a0;
    o[32 + l] = a1;
    o[64 + l] = a2;
}

// ---------------------------------------------------------------------------
// Launch. Stream fork: {zero, bucket} on s2 overlap {xconv, gemm_y} on the
// capture (default) stream; event join before aggregate.
// Inputs: x[N*D] f32, edge_index[2*E] i32, edge_weight[E] f32,
//         pagerank[N] f32, W[D*D] f32, b[D] f32. Output f32 [N,D].
// ---------------------------------------------------------------------------
extern "C" void kernel_launch(void* const* d_in, const int* in_sizes, int n_in,
                              void* d_out, int out_size) {
    const float* x  = (const float*)d_in[0];
    const int*   ei = (const int*)  d_in[1];
    const float* ew = (const float*)d_in[2];
    const float* pr = (const float*)d_in[3];
    const float* Wm = (const float*)d_in[4];
    const float* b  = (const float*)d_in[5];
    float* out = (float*)d_out;

    int N = in_sizes[0] / D;
    int E = in_sizes[1] / 2;

    static cudaStream_t s2 = nullptr;
    static cudaEvent_t ev_fork = nullptr, ev_join = nullptr;
    if (s2 == nullptr) {
        cudaStreamCreateWithFlags(&s2, cudaStreamNonBlocking);
        cudaEventCreateWithFlags(&ev_fork, cudaEventDisableTiming);
        cudaEventCreateWithFlags(&ev_join, cudaEventDisableTiming);
        const int gemm_smem = (D * LDP + 2 * NTILE * LDP) * (int)sizeof(uint32_t);
        cudaFuncSetAttribute(gemm_y_kernel,
                             cudaFuncAttributeMaxDynamicSharedMemorySize, gemm_smem);
    }
    const int gemm_smem = (D * LDP + 2 * NTILE * LDP) * (int)sizeof(uint32_t);

    // fork: bucket chain on s2
    cudaEventRecord(ev_fork, 0);
    cudaStreamWaitEvent(s2, ev_fork, 0);
    zero_kernel<<<(N + 255) / 256, 256, 0, s2>>>(N);
    int nthread = (E + EPT - 1) / EPT;
    bucket_kernel<<<(nthread + 255) / 256, 256, 0, s2>>>(ei, ew, pr, E);
    cudaEventRecord(ev_join, s2);

    // main stream: xconv -> gemm_y (independent of buckets)
    int n4 = N * D / 4;
    xconv_kernel<<<(n4 + 255) / 256, 256>>>(x, Wm, n4);

    int ntiles = (N + NTILE - 1) / NTILE;
    int grid = 296;
    if (grid > ntiles) grid = ntiles;
    gemm_y_kernel<<<grid, 256, gemm_smem>>>(N, ntiles);

    // join, then final aggregation straight into out
    cudaStreamWaitEvent(0, ev_join, 0);
    aggregate_kernel<<<(N + 7) / 8, 256>>>(b, out, N);
}